// round 15
// baseline (speedup 1.0000x reference)
#include <cuda_runtime.h>
#include <cuda_fp16.h>
#include <cstdint>

// CIN cross-network via warp-level HMMA, single-pass fp16 with x0 folded
// into the A operand (zf = hmul2(xk_frag, dup(x0))), D chained across all
// k-steps. 1 CTA x 512 threads, TB=16 batch rows (256 MMA rows), warp tile
// 32r x 32c (8 row-warps x 2 col-warps). 64 KB W stages (32 k-slots),
// double-buffered -> 10 stage barriers per block. d-reduce via shfl from D
// (fp32 exact); xk stored fp16 only (feeds next layer's fp16 A-frags).

#define THREADS 512
#define TB 16

// smem byte offsets
#define O_XH  0        // half xk[256][64]        32 KB
#define O_X0H 32768    // uint32 x0h[256][32]     32 KB (dup'd half2)
#define O_WF  65536    // 2 x 64 KB stage buffers
#define SM_TOTAL 196608

// 80 chunks x 1024 uint2 (8 KB): [ci][slot][nt][lane] = fp16x2 pair of W
__device__ __align__(16) uint2 WFRAG2[80 * 1024];

__device__ __forceinline__ uint32_t pack_h2(float lo, float hi) {
    uint32_t r;
    asm("cvt.rn.f16x2.f32 %0, %1, %2;" : "=r"(r) : "f"(hi), "f"(lo));
    return r;
}
__device__ __forceinline__ uint32_t hmul2(uint32_t a, uint32_t b) {
    uint32_t r;
    asm("mul.rn.f16x2 %0, %1, %2;" : "=r"(r) : "r"(a), "r"(b));
    return r;
}
__device__ __forceinline__ void mma_acc(float d[4], const uint4& a, const uint2& b) {
    asm("mma.sync.aligned.m16n8k16.row.col.f32.f16.f16.f32 "
        "{%0,%1,%2,%3}, {%4,%5,%6,%7}, {%8,%9}, {%0,%1,%2,%3};"
        : "+f"(d[0]), "+f"(d[1]), "+f"(d[2]), "+f"(d[3])
        : "r"(a.x), "r"(a.y), "r"(a.z), "r"(a.w), "r"(b.x), "r"(b.y));
}
__device__ __forceinline__ uint32_t smem_u32(const void* p) {
    uint32_t a;
    asm("{ .reg .u64 t; cvta.to.shared.u64 t, %1; cvt.u32.u64 %0, t; }"
        : "=r"(a) : "l"(p));
    return a;
}
__device__ __forceinline__ void cp_async16(uint32_t saddr, const void* gaddr) {
    asm volatile("cp.async.cg.shared.global [%0], [%1], 16;"
                 :: "r"(saddr), "l"(gaddr) : "memory");
}
#define CP_COMMIT() asm volatile("cp.async.commit_group;" ::: "memory")
#define CP_WAIT0()  asm volatile("cp.async.wait_group 0;" ::: "memory")

// ---------- prep: convert W to fp16 B-fragments ----------
// ci 0..79 (L0:0-15, L1:16-47, L2:48-79)
__global__ void prep_kernel(const float* __restrict__ W0,
                            const float* __restrict__ W1,
                            const float* __restrict__ W2)
{
    int t = blockIdx.x * blockDim.x + threadIdx.x;
    if (t >= 80 * 4 * 8 * 32) return;
    int lane = t & 31;
    int ntg  = (t >> 5) & 7;
    int slot = (t >> 8) & 3;
    int ci   = t >> 10;
    const float* Wl; int c;
    if (ci < 16)      { Wl = W0; c = ci; }
    else if (ci < 48) { Wl = W1; c = ci - 16; }
    else              { Wl = W2; c = ci - 48; }
    int kk = ntg * 8 + (lane >> 2);
    int c0 = (lane & 3) * 2;
    const float* p = Wl + c * 4096 + slot * 1024 + c0 * 64 + kk;
    WFRAG2[ci * 1024 + (slot * 8 + ntg) * 32 + lane] =
        make_uint2(pack_h2(p[0], p[64]), pack_h2(p[512], p[576]));
}

// ---------- main ----------
// build register A-frags from fp16 xk (stored as uint32 = half2 pairs)
template<int NKS>
__device__ __forceinline__ void build_A(const uint32_t* xk_h2, uint4 AH[2][4],
                                        int wr, int tg, int tc)
{
#pragma unroll
    for (int rg = 0; rg < 2; rg++)
#pragma unroll
        for (int ks = 0; ks < NKS; ks++) {
            int r = wr * 32 + rg * 16 + tg;
            const uint32_t* p = xk_h2 + r * 32 + ks * 8 + tc;
            AH[rg][ks] = make_uint4(p[0], p[8 * 32], p[4], p[8 * 32 + 4]);
        }
}

// one 64 KB stage = 32 k-slots = 32/KSM m-values (KSM = k-steps per m)
template<int KSM>
__device__ __forceinline__ void compute_stage(
    const uint2* __restrict__ WFb, const uint4 AH[2][4],
    const uint32_t* __restrict__ x0h, int s, int wr, int wc, int tg, int lane,
    float D[2][4][4])
{
    const int MPS = 32 / KSM;
#pragma unroll
    for (int mm = 0; mm < MPS; mm++) {
        const int m = s * MPS + mm;
        uint32_t s0[2], s1[2];
#pragma unroll
        for (int rg = 0; rg < 2; rg++) {
            int r0 = wr * 32 + rg * 16 + tg;
            s0[rg] = x0h[r0 * 32 + m];
            s1[rg] = x0h[(r0 + 8) * 32 + m];
        }
#pragma unroll
        for (int i = 0; i < KSM; i++) {
            const int si = mm * KSM + i;
            const uint2* bp = WFb + si * 256 + wc * 128 + lane;
            uint2 Bv[4];
#pragma unroll
            for (int nt = 0; nt < 4; nt++) Bv[nt] = bp[nt * 32];
#pragma unroll
            for (int rg = 0; rg < 2; rg++) {
                uint4 zf;
                zf.x = hmul2(AH[rg][i].x, s0[rg]);
                zf.y = hmul2(AH[rg][i].y, s1[rg]);
                zf.z = hmul2(AH[rg][i].z, s0[rg]);
                zf.w = hmul2(AH[rg][i].w, s1[rg]);
#pragma unroll
                for (int nt = 0; nt < 4; nt++)
                    mma_acc(D[rg][nt], zf, Bv[nt]);
            }
        }
    }
}

// fetch one 64 KB stage (8 consecutive 8 KB chunks) via cp.async
__device__ __forceinline__ void fetch_stage(uint32_t sdst, int ci, int tid) {
#pragma unroll
    for (int q = 0; q < 8; q++) {
        int off = (q * 512 + tid) * 16;
        cp_async16(sdst + off, (const char*)WFRAG2 + (size_t)ci * 8192 + off);
    }
    CP_COMMIT();
}

template<int KSM, bool LAST>
__device__ __forceinline__ void layer(
    int ci0, int nextci0, int L,
    const uint32_t* x0h, uint32_t* xk_h2, uint2* WFs, uint32_t wf_sm,
    uint4 AH[2][4],
    float* out, long long bg0,
    int tid, int lane, int wr, int wc, int tg, int tc)
{
    const int NS = (KSM == 2) ? 2 : 4;   // stages this layer
    float D[2][4][4];
#pragma unroll
    for (int rg = 0; rg < 2; rg++)
#pragma unroll
        for (int nt = 0; nt < 4; nt++)
#pragma unroll
            for (int j = 0; j < 4; j++) D[rg][nt][j] = 0.f;

    int buf = 0;
    for (int s = 0; s < NS; s++) {
        if (s + 1 < NS) fetch_stage(wf_sm + (buf ^ 1) * 65536, ci0 + 8 * (s + 1), tid);
        else if (!LAST) fetch_stage(wf_sm + (buf ^ 1) * 65536, nextci0, tid);
        compute_stage<KSM>(WFs + buf * 8192, AH, x0h, s, wr, wc, tg, lane, D);
        CP_WAIT0();
        __syncthreads();
        buf ^= 1;
    }

    // epilogue: relu (fp32), d-reduce via shfl from D, store out;
    // store fp16 xk for next layer's A-frags
#pragma unroll
    for (int rg = 0; rg < 2; rg++) {
        int b_loc = wr * 2 + rg;
        int r0 = wr * 32 + rg * 16 + tg;
#pragma unroll
        for (int nt = 0; nt < 4; nt++) {
            int cb = wc * 32 + nt * 8 + tc * 2;
            float r00 = fmaxf(D[rg][nt][0], 0.f), r01 = fmaxf(D[rg][nt][1], 0.f);
            float r10 = fmaxf(D[rg][nt][2], 0.f), r11 = fmaxf(D[rg][nt][3], 0.f);
            if (!LAST) {
                xk_h2[r0 * 32 + (cb >> 1)]       = pack_h2(r00, r01);
                xk_h2[(r0 + 8) * 32 + (cb >> 1)] = pack_h2(r10, r11);
            }
            float sc0 = r00 + r10, sc1 = r01 + r11;   // rows tg, tg+8
            sc0 += __shfl_xor_sync(0xffffffffu, sc0, 4);
            sc1 += __shfl_xor_sync(0xffffffffu, sc1, 4);
            sc0 += __shfl_xor_sync(0xffffffffu, sc0, 8);
            sc1 += __shfl_xor_sync(0xffffffffu, sc1, 8);
            sc0 += __shfl_xor_sync(0xffffffffu, sc0, 16);
            sc1 += __shfl_xor_sync(0xffffffffu, sc1, 16);
            if (tg == 0)
                *(float2*)&out[(bg0 + b_loc) * 192 + L * 64 + cb] =
                    make_float2(sc0, sc1);
        }
    }
    if (!LAST) {
        __syncthreads();               // xk stores visible before build_A reads
        build_A<4>(xk_h2, AH, wr, tg, tc);
        __syncthreads();
    }
}

__global__ void __launch_bounds__(THREADS, 1)
cin_kernel(const float* __restrict__ emb,
           const float* __restrict__ W0,
           const float* __restrict__ W1,
           const float* __restrict__ W2,
           float* __restrict__ out)
{
    extern __shared__ char smem[];
    uint32_t* xk_h2 = (uint32_t*)(smem + O_XH);
    __half*   xk_h  = (__half*)(smem + O_XH);
    uint32_t* x0h   = (uint32_t*)(smem + O_X0H);
    uint2*    WFs   = (uint2*)(smem + O_WF);
    float*    x0st  = (float*)(smem + O_WF + 65536);   // staging in buf1
    const uint32_t wf_sm = smem_u32(smem + O_WF);

    const int tid = threadIdx.x, lane = tid & 31, w = tid >> 5;
    const int wr = w >> 1;        // row-warp: rows 32*wr .. 32*wr+31
    const int wc = w & 1;         // col-warp: cols 32*wc .. 32*wc+31
    const int tg = lane >> 2, tc = lane & 3;
    const long long bg0 = (long long)blockIdx.x * TB;

    // stage x0 fp32 into WF buf1 (coalesced), prefetch stage 0 into buf0
    {
        const float4* g = (const float4*)(emb + bg0 * 512);
        float4* sp = (float4*)x0st;
#pragma unroll
        for (int i = 0; i < 4; i++) sp[tid + i * THREADS] = g[tid + i * THREADS];
    }
    fetch_stage(wf_sm, 0, tid);
    __syncthreads();

    // xk fp16 [r][h] = x0[b][h][d] (h < 32);  x0h[r][m] = dup_h2(x0[b][m][d])
#pragma unroll
    for (int i = tid; i < 8192; i += THREADS) {
        int r = i >> 5, h = i & 31;
        xk_h[r * 64 + h] = __float2half(x0st[((r >> 4) << 9) + h * 16 + (r & 15)]);
    }
#pragma unroll
    for (int i = 0; i < 16; i++) {
        int e = tid * 16 + i;          // e = r*32 + m
        int r = e >> 5, m = e & 31;
        float v = x0st[((r >> 4) << 9) + m * 16 + (r & 15)];
        x0h[e] = pack_h2(v, v);
    }
    CP_WAIT0();
    __syncthreads();                   // buf0 ready; staging reads done

    uint4 AH[2][4];
    build_A<2>(xk_h2, AH, wr, tg, tc);

    layer<2, false>(0,  16, 0, x0h, xk_h2, WFs, wf_sm, AH, out, bg0,
                    tid, lane, wr, wc, tg, tc);
    layer<4, false>(16, 48, 1, x0h, xk_h2, WFs, wf_sm, AH, out, bg0,
                    tid, lane, wr, wc, tg, tc);
    layer<4, true >(48, 0,  2, x0h, xk_h2, WFs, wf_sm, AH, out, bg0,
                    tid, lane, wr, wc, tg, tc);
}

extern "C" void kernel_launch(void* const* d_in, const int* in_sizes, int n_in,
                              void* d_out, int out_size)
{
    const float* emb = (const float*)d_in[0];
    const float* W0  = (const float*)d_in[1];
    const float* W1  = (const float*)d_in[2];
    const float* W2  = (const float*)d_in[3];
    float* out = (float*)d_out;

    prep_kernel<<<320, 256>>>(W0, W1, W2);
    cudaFuncSetAttribute(cin_kernel,
                         cudaFuncAttributeMaxDynamicSharedMemorySize, SM_TOTAL);
    cin_kernel<<<16384 / TB, THREADS, SM_TOTAL>>>(emb, W0, W1, W2, out);
}

// round 16
// speedup vs baseline: 1.0138x; 1.0138x over previous
#include <cuda_runtime.h>
#include <cuda_fp16.h>
#include <cstdint>

// CIN cross-network via warp-level HMMA, single-pass fp16 with x0 folded
// into the A operand (zf = hmul2(xk_frag, dup(x0))), D chained across all
// k-steps. 2 CTAs x 256 threads, TB=8. Warp tile 32r x 32c. W fp16 B-frags
// precomputed by prep_kernel, streamed via cp.async in 32 KB stages.
// NEW: B fragments explicitly double-buffered in registers — slot si+1's
// LDS issues before slot si's MMAs, hiding the 29-cycle smem latency.

#define THREADS 256
#define TB 8

// smem byte offsets (x0h is built in-place over the fp32 x0 staging area)
#define O_X0 0         // fp32 x0 [4096] -> then uint32 x0h[128][32]  16 KB
#define O_XK 16384     // float[128*64]      32 KB
#define O_WF 49152     // 2 x 32 KB W-frag stage buffers
#define SM_TOTAL 114688

// 80 chunks x 1024 uint2 (8 KB): [ci][slot][nt][lane] = fp16x2 pair of W
__device__ __align__(16) uint2 WFRAG2[80 * 1024];

__device__ __forceinline__ uint32_t pack_h2(float lo, float hi) {
    uint32_t r;
    asm("cvt.rn.f16x2.f32 %0, %1, %2;" : "=r"(r) : "f"(hi), "f"(lo));
    return r;
}
__device__ __forceinline__ uint32_t hmul2(uint32_t a, uint32_t b) {
    uint32_t r;
    asm("mul.rn.f16x2 %0, %1, %2;" : "=r"(r) : "r"(a), "r"(b));
    return r;
}
__device__ __forceinline__ void mma_acc(float d[4], const uint4& a, const uint2& b) {
    asm("mma.sync.aligned.m16n8k16.row.col.f32.f16.f16.f32 "
        "{%0,%1,%2,%3}, {%4,%5,%6,%7}, {%8,%9}, {%0,%1,%2,%3};"
        : "+f"(d[0]), "+f"(d[1]), "+f"(d[2]), "+f"(d[3])
        : "r"(a.x), "r"(a.y), "r"(a.z), "r"(a.w), "r"(b.x), "r"(b.y));
}
__device__ __forceinline__ uint32_t smem_u32(const void* p) {
    uint32_t a;
    asm("{ .reg .u64 t; cvta.to.shared.u64 t, %1; cvt.u32.u64 %0, t; }"
        : "=r"(a) : "l"(p));
    return a;
}
__device__ __forceinline__ void cp_async16(uint32_t saddr, const void* gaddr) {
    asm volatile("cp.async.cg.shared.global [%0], [%1], 16;"
                 :: "r"(saddr), "l"(gaddr) : "memory");
}
#define CP_COMMIT() asm volatile("cp.async.commit_group;" ::: "memory")
#define CP_WAIT0()  asm volatile("cp.async.wait_group 0;" ::: "memory")

// ---------- prep: convert W to fp16 B-fragments ----------
// ci 0..79 (L0:0-15, L1:16-47, L2:48-79)
__global__ void prep_kernel(const float* __restrict__ W0,
                            const float* __restrict__ W1,
                            const float* __restrict__ W2)
{
    int t = blockIdx.x * blockDim.x + threadIdx.x;
    if (t >= 80 * 4 * 8 * 32) return;
    int lane = t & 31;
    int ntg  = (t >> 5) & 7;
    int slot = (t >> 8) & 3;
    int ci   = t >> 10;
    const float* Wl; int c;
    if (ci < 16)      { Wl = W0; c = ci; }
    else if (ci < 48) { Wl = W1; c = ci - 16; }
    else              { Wl = W2; c = ci - 48; }
    int kk = ntg * 8 + (lane >> 2);
    int c0 = (lane & 3) * 2;
    const float* p = Wl + c * 4096 + slot * 1024 + c0 * 64 + kk;
    WFRAG2[ci * 1024 + (slot * 8 + ntg) * 32 + lane] =
        make_uint2(pack_h2(p[0], p[64]), pack_h2(p[512], p[576]));
}

// ---------- main ----------
// build register A-frags (fp16 xk) from xk_s [r][64], 2 row-groups x NKS ksteps
template<int NKS>
__device__ __forceinline__ void build_A(const float* xk_s, uint4 AH[2][4],
                                        int wr, int tg, int c0)
{
#pragma unroll
    for (int rg = 0; rg < 2; rg++)
#pragma unroll
        for (int ks = 0; ks < NKS; ks++) {
            const float* p = xk_s + (wr * 32 + rg * 16 + tg) * 64 + ks * 16 + c0;
            float2 v0 = *(const float2*)(p);
            float2 v1 = *(const float2*)(p + 8 * 64);
            float2 v2 = *(const float2*)(p + 8);
            float2 v3 = *(const float2*)(p + 8 * 64 + 8);
            AH[rg][ks] = make_uint4(pack_h2(v0.x, v0.y), pack_h2(v1.x, v1.y),
                                    pack_h2(v2.x, v2.y), pack_h2(v3.x, v3.y));
        }
}

// one 32 KB stage = 16 k-slots = 16/KSM m-values (KSM = k-steps per m).
// B fragments double-buffered in registers: slot si+1's loads issue before
// slot si's MMA burst.
template<int KSM>
__device__ __forceinline__ void compute_stage(
    const uint2* __restrict__ WFb, const uint4 AH[2][4],
    const uint32_t* __restrict__ x0h, int s, int wr, int wc, int tg, int lane,
    float D[2][4][4])
{
    const int MPS = 16 / KSM;
    uint2 Bv[2][4];
    {
        const uint2* bp = WFb + wc * 128 + lane;
#pragma unroll
        for (int nt = 0; nt < 4; nt++) Bv[0][nt] = bp[nt * 32];
    }
    uint32_t s0[2], s1[2];
#pragma unroll
    for (int si = 0; si < 16; si++) {
        const int cur = si & 1;
        // prefetch next slot's B fragments first (latency overlapped by MMAs)
        if (si + 1 < 16) {
            const uint2* bp = WFb + (si + 1) * 256 + wc * 128 + lane;
#pragma unroll
            for (int nt = 0; nt < 4; nt++) Bv[cur ^ 1][nt] = bp[nt * 32];
        }
        const int mm = si / KSM;
        const int i  = si % KSM;
        if (i == 0) {                       // new m: load fold scalars
            const int m = s * MPS + mm;
#pragma unroll
            for (int rg = 0; rg < 2; rg++) {
                int r0 = wr * 32 + rg * 16 + tg;
                s0[rg] = x0h[r0 * 32 + m];
                s1[rg] = x0h[(r0 + 8) * 32 + m];
            }
        }
#pragma unroll
        for (int rg = 0; rg < 2; rg++) {
            uint4 zf;
            zf.x = hmul2(AH[rg][i].x, s0[rg]);
            zf.y = hmul2(AH[rg][i].y, s1[rg]);
            zf.z = hmul2(AH[rg][i].z, s0[rg]);
            zf.w = hmul2(AH[rg][i].w, s1[rg]);
#pragma unroll
            for (int nt = 0; nt < 4; nt++)
                mma_acc(D[rg][nt], zf, Bv[cur][nt]);
        }
    }
}

// fetch one 32 KB stage (4 consecutive 8 KB chunks) via cp.async
__device__ __forceinline__ void fetch_stage(uint32_t sdst, int ci, int tid) {
#pragma unroll
    for (int q = 0; q < 8; q++) {
        int off = (q * 256 + tid) * 16;
        cp_async16(sdst + off, (const char*)WFRAG2 + (size_t)ci * 8192 + off);
    }
    CP_COMMIT();
}

template<int KSM, bool LAST>
__device__ __forceinline__ void layer(
    int ci0, int nextci0, int L,
    const uint32_t* x0h, float* xk_s, uint2* WFs, uint32_t wf_sm,
    uint4 AH[2][4],
    float* out, long long bg0,
    int tid, int lane, int wr, int wc, int tg, int tc)
{
    const int NS = (KSM == 2) ? 4 : 8;   // stages this layer
    float D[2][4][4];
#pragma unroll
    for (int rg = 0; rg < 2; rg++)
#pragma unroll
        for (int nt = 0; nt < 4; nt++)
#pragma unroll
            for (int j = 0; j < 4; j++) D[rg][nt][j] = 0.f;

    int buf = 0;
    for (int s = 0; s < NS; s++) {
        if (s + 1 < NS) fetch_stage(wf_sm + (buf ^ 1) * 32768, ci0 + 4 * (s + 1), tid);
        else if (!LAST) fetch_stage(wf_sm + (buf ^ 1) * 32768, nextci0, tid);
        compute_stage<KSM>(WFs + buf * 4096, AH, x0h, s, wr, wc, tg, lane, D);
        CP_WAIT0();
        __syncthreads();
        buf ^= 1;
    }

    // relu -> xk_s [r][k]
#pragma unroll
    for (int rg = 0; rg < 2; rg++) {
        int r0 = wr * 32 + rg * 16 + tg;
#pragma unroll
        for (int nt = 0; nt < 4; nt++) {
            int cb = wc * 32 + nt * 8 + tc * 2;
            *(float2*)&xk_s[r0 * 64 + cb] =
                make_float2(fmaxf(D[rg][nt][0], 0.f), fmaxf(D[rg][nt][1], 0.f));
            *(float2*)&xk_s[(r0 + 8) * 64 + cb] =
                make_float2(fmaxf(D[rg][nt][2], 0.f), fmaxf(D[rg][nt][3], 0.f));
        }
    }
    __syncthreads();

    // d-reduce -> out
    {
        int ob = tid >> 5, ok = (tid & 31) * 2;
        float s0 = 0.f, s1 = 0.f;
#pragma unroll
        for (int d = 0; d < 16; d++) {
            float2 v = *(const float2*)&xk_s[(ob * 16 + d) * 64 + ok];
            s0 += v.x; s1 += v.y;
        }
        *(float2*)&out[(bg0 + ob) * 192 + L * 64 + ok] = make_float2(s0, s1);
    }
    if (!LAST) {
        int c0 = tc * 2;
        build_A<4>(xk_s, AH, wr, tg, c0);
    }
    __syncthreads();
}

__global__ void __launch_bounds__(THREADS, 2)
cin_kernel(const float* __restrict__ emb,
           const float* __restrict__ W0,
           const float* __restrict__ W1,
           const float* __restrict__ W2,
           float* __restrict__ out)
{
    extern __shared__ char smem[];
    float*    x0_s = (float*)(smem + O_X0);     // fp32 staging, then...
    uint32_t* x0h  = (uint32_t*)(smem + O_X0);  // ...dup'd half2 [r][m]
    float* xk_s = (float*)(smem + O_XK);
    uint2* WFs  = (uint2*)(smem + O_WF);
    const uint32_t wf_sm = smem_u32(smem + O_WF);

    const int tid = threadIdx.x, lane = tid & 31, w = tid >> 5;
    const int wr = w & 3;         // row-warp: rows 32*wr .. 32*wr+31
    const int wc = w >> 2;        // col-warp: cols 32*wc .. 32*wc+31
    const int tg = lane >> 2, tc = lane & 3;
    const int c0 = tc * 2;
    const long long bg0 = (long long)blockIdx.x * TB;

    // load x0 fp32 (coalesced)
    {
        const float4* g = (const float4*)(emb + bg0 * 512);
        float4* sp = (float4*)x0_s;
#pragma unroll
        for (int i = 0; i < 4; i++) sp[tid + i * THREADS] = g[tid + i * THREADS];
    }
    // prefetch stage 0 (chunks 0..3)
    fetch_stage(wf_sm, 0, tid);
    __syncthreads();

    // xk_s[r][h] = x0[b][h][d]  (r = b*16+d, h < 32), and stage this
    // thread's 16 x0h entries in regs for the in-place transmute
    float v[16];
#pragma unroll
    for (int i = tid; i < 4096; i += THREADS) {
        int r = i >> 5, h = i & 31;
        xk_s[r * 64 + h] = x0_s[((r >> 4) << 9) + h * 16 + (r & 15)];
    }
#pragma unroll
    for (int i = 0; i < 16; i++) {
        int e = tid * 16 + i;            // e = r*32 + m
        int r = e >> 5, m = e & 31;
        v[i] = x0_s[((r >> 4) << 9) + m * 16 + (r & 15)];
    }
    __syncthreads();
    // x0h[r*32+m] = dup_h2(x0[b,m,d]) — overwrites the fp32 staging area
#pragma unroll
    for (int i = 0; i < 16; i++) {
        uint32_t d2 = pack_h2(v[i], v[i]);
        x0h[tid * 16 + i] = d2;
    }
    CP_WAIT0();
    __syncthreads();

    uint4 AH[2][4];
    build_A<2>(xk_s, AH, wr, tg, c0);

    layer<2, false>(0,  16, 0, x0h, xk_s, WFs, wf_sm, AH, out, bg0,
                    tid, lane, wr, wc, tg, tc);
    layer<4, false>(16, 48, 1, x0h, xk_s, WFs, wf_sm, AH, out, bg0,
                    tid, lane, wr, wc, tg, tc);
    layer<4, true >(48, 0,  2, x0h, xk_s, WFs, wf_sm, AH, out, bg0,
                    tid, lane, wr, wc, tg, tc);
}

extern "C" void kernel_launch(void* const* d_in, const int* in_sizes, int n_in,
                              void* d_out, int out_size)
{
    const float* emb = (const float*)d_in[0];
    const float* W0  = (const float*)d_in[1];
    const float* W1  = (const float*)d_in[2];
    const float* W2  = (const float*)d_in[3];
    float* out = (float*)d_out;

    prep_kernel<<<320, 256>>>(W0, W1, W2);
    cudaFuncSetAttribute(cin_kernel,
                         cudaFuncAttributeMaxDynamicSharedMemorySize, SM_TOTAL);
    cin_kernel<<<16384 / TB, THREADS, SM_TOTAL>>>(emb, W0, W1, W2, out);
}